// round 12
// baseline (speedup 1.0000x reference)
#include <cuda_runtime.h>
#include <cuda_bf16.h>

// PointGNN, algebraically reduced, single persistent kernel, 1 block/SM,
// per-step weights staged via background cp.async into big dynamic smem.
//   adj(i) = { j : |x_i - x_j|^2 < 0.05 }  (fixed; self always in-set)
//   F_t[j]   = MLP_f([0,0,0,state_j])      (per NODE, not per edge)
//   agg_t[i] = max_{j in adj(i)} F_t[j]    (channelwise; F>=0 so 0-floor exact)
//   state   += relu(MLP_g(agg_t))
// h-MLP provably dead. TPB=768 halves each thread's serial chain vs TPB=384;
// float4 activation loads cut LDS issue count ~40%. GRID=128 <= 148 SMs ->
// one co-resident block per SM: software grid barrier is deadlock-free.

#define MM    384
#define NODES (4*MM)
#define MASKW 12
#define BN    12
#define TPB   768
#define GRID  (NODES/BN)   // 128
#define MAXD  128

// dynamic smem layout (floats unless noted):
//   sG1 8192 | sG2 2048 | sF2 8192 | sF3 16384 | sA 1536 | sB 1536 | sG3 96
//   | sN 1536 u16 | sD 12 int     => 155,056 bytes
#define SMEM_BYTES 155056

__device__ float    g_Fbuf[2][NODES * 128];
__device__ unsigned g_bar;   // monotonic; wrap-safe barrier

__device__ __forceinline__ void cpa(float* dst, const float* src, int nfloats) {
    for (int idx = threadIdx.x * 4; idx < nfloats; idx += TPB * 4) {
        unsigned sa = (unsigned)__cvta_generic_to_shared(dst + idx);
        asm volatile("cp.async.cg.shared.global [%0], [%1], 16;"
                     :: "r"(sa), "l"(src + idx));
    }
}
__device__ __forceinline__ void cpa_commit() {
    asm volatile("cp.async.commit_group;");
}
template<int N> __device__ __forceinline__ void cpa_wait() {
    asm volatile("cp.async.wait_group %0;" :: "n"(N));
}

// grid-wide barrier: monotonic ticket counter, wrap-safe compare
__device__ __forceinline__ void grid_bar() {
    __syncthreads();
    if (threadIdx.x == 0) {
        __threadfence();
        unsigned v = atomicAdd(&g_bar, 1u);
        unsigned target = v - (v % (unsigned)GRID) + (unsigned)GRID;
        unsigned cur;
        do {
            asm volatile("ld.acquire.gpu.u32 %0, [%1];" : "=r"(cur) : "l"(&g_bar));
        } while ((int)(cur - target) < 0);
    }
    __syncthreads();
}

// ---------------------------------------------------------------------------
__global__ __launch_bounds__(TPB) void pointgnn_persistent(
    const float* x, float* state,
    const float* fW1, const float* fb1, const float* fW2, const float* fb2,
    const float* fW3, const float* fb3,
    const float* gW1, const float* gb1, const float* gW2, const float* gb2,
    const float* gW3, const float* gb3)
{
    extern __shared__ float sm[];
    float*          sG1 = sm;                 // 8192
    float*          sG2 = sG1 + 8192;         // 2048
    float*          sF2 = sG2 + 2048;         // 8192
    float*          sF3 = sF2 + 8192;         // 16384
    float*          sA  = sF3 + 16384;        // 12 x 128
    float*          sB  = sA + 1536;          // 12 x 128
    float*          sG3 = sB + 1536;          // 96
    unsigned short* sN  = (unsigned short*)(sG3 + 96);   // 12 x 128
    int*            sD  = (int*)(sN + BN*MAXD);          // 12

    const int t    = threadIdx.x;
    const int base = blockIdx.x * BN;        // 12 nodes, same batch (384%12==0)
    const int n    = base / MM;
    const int c    = t & 127;                // channel lane (128-wide phases)
    const int g6   = t >> 7;                 // 0..5 -> node pair
    const int k64  = t & 63;
    const int n12  = t >> 6;                 // 0..11 -> node (64-wide phases)

    // ---- stage f0 weights immediately (overlap adjacency build) ----
    cpa(sF2, fW2, 8192);  cpa_commit();      // group: F2
    cpa(sF3, fW3, 16384); cpa_commit();      // group: F3

    // ---- one-time prefetch: all 3 steps' biases + state + fW1 rows ----
    float bf1[3], bf2[3], bf3[3], bg1[3], bg2[3], bg3s[3];
    float w1a[3], w1b[3], w1c[3];
    #pragma unroll
    for (int s = 0; s < 3; s++) {
        bf1[s] = fb1[s*64  + k64];
        bf2[s] = fb2[s*128 + c];
        bf3[s] = fb3[s*128 + c];
        bg1[s] = gb1[s*64  + k64];
        bg2[s] = gb2[s*32  + (t & 31)];
        w1a[s] = fW1[s*384 + 3*64 + k64];
        w1b[s] = fW1[s*384 + 4*64 + k64];
        w1c[s] = fW1[s*384 + 5*64 + k64];
    }
    float stv = 0.f;
    if (t < BN*3) {
        stv = x[base*3 + t];
        #pragma unroll
        for (int s = 0; s < 3; s++) bg3s[s] = gb3[s*3 + t % 3];
    }

    // ---- adjacency (once, pure smem): warp-per-node popc compaction ----
    {
        const int warp = t >> 5, lane = t & 31;   // warps 0..11 = nodes
        if (warp < BN) {
            const int i = base + warp;
            float xi0 = x[i*3+0], xi1 = x[i*3+1], xi2 = x[i*3+2];
            int cnt = 0;
            #pragma unroll
            for (int wc = 0; wc < MASKW; wc++) {
                int j = wc*32 + lane;
                const float* xj = x + (n*MM + j)*3;
                float dx = xi0 - xj[0], dy = xi1 - xj[1], dz = xi2 - xj[2];
                // non-contracted to match reference's (diff*diff).sum() compare
                float s2 = __fadd_rn(__fadd_rn(__fmul_rn(dx,dx), __fmul_rn(dy,dy)),
                                     __fmul_rn(dz,dz));
                bool pred = s2 < 0.05f;
                unsigned m = __ballot_sync(0xffffffffu, pred);
                int pos = cnt + __popc(m & ((1u << lane) - 1u));
                if (pred && pos < MAXD) sN[warp*MAXD + pos] = (unsigned short)j;
                cnt += __popc(m);
            }
            if (lane == 0) {
                int cl = cnt < MAXD ? cnt : MAXD;
                int padded = (cl + 7) & ~7;        // pad to x8 for ILP-8 max
                unsigned short self = (unsigned short)(i - n*MM);
                for (int p = cl; p < padded; p++) sN[warp*MAXD + p] = self;
                sD[warp] = padded;
            }
        }
    }
    if (t < BN*3) sB[(t/3)*128 + t%3] = stv;       // state := x
    __syncthreads();

    // ================= F0 = MLP_f(x) =================
    {
        // layer1 (rows 3..5 only, weights in regs): 1 output/thread
        {
            float acc = bf1[0];
            acc = fmaf(sB[n12*128+0], w1a[0], acc);
            acc = fmaf(sB[n12*128+1], w1b[0], acc);
            acc = fmaf(sB[n12*128+2], w1c[0], acc);
            sA[n12*128 + k64] = fmaxf(acc, 0.f);
        }
        cpa_wait<1>();        // F2 staged (F3 may still be in flight)
        __syncthreads();

        // layer2: 64 -> 128, 2 nodes/thread, float4 act loads
        float a20 = bf2[0], a21 = bf2[0];
        const float* A0 = sA + (g6*2)*128, * A1 = A0 + 128;
        #pragma unroll
        for (int kk = 0; kk < 64; kk += 4) {
            float4 v0 = *(const float4*)(A0 + kk);
            float4 v1 = *(const float4*)(A1 + kk);
            float w0 = sF2[(kk+0)*128 + c], w1 = sF2[(kk+1)*128 + c];
            float w2 = sF2[(kk+2)*128 + c], w3 = sF2[(kk+3)*128 + c];
            a20 = fmaf(v0.x, w0, a20); a21 = fmaf(v1.x, w0, a21);
            a20 = fmaf(v0.y, w1, a20); a21 = fmaf(v1.y, w1, a21);
            a20 = fmaf(v0.z, w2, a20); a21 = fmaf(v1.z, w2, a21);
            a20 = fmaf(v0.w, w3, a20); a21 = fmaf(v1.w, w3, a21);
        }
        sB[(g6*2  )*128 + c] = fmaxf(a20, 0.f);
        sB[(g6*2+1)*128 + c] = fmaxf(a21, 0.f);
        cpa_wait<0>();        // F3 staged
        __syncthreads();

        // layer3: 128 -> 128 single pass, 2 nodes/thread, float4 act loads
        float a30 = bf3[0], a31 = bf3[0];
        const float* B0 = sB + (g6*2)*128, * B1 = B0 + 128;
        #pragma unroll 8
        for (int kk = 0; kk < 128; kk += 4) {
            float4 v0 = *(const float4*)(B0 + kk);
            float4 v1 = *(const float4*)(B1 + kk);
            float w0 = sF3[(kk+0)*128 + c], w1 = sF3[(kk+1)*128 + c];
            float w2 = sF3[(kk+2)*128 + c], w3 = sF3[(kk+3)*128 + c];
            a30 = fmaf(v0.x, w0, a30); a31 = fmaf(v1.x, w0, a31);
            a30 = fmaf(v0.y, w1, a30); a31 = fmaf(v1.y, w1, a31);
            a30 = fmaf(v0.z, w2, a30); a31 = fmaf(v1.z, w2, a31);
            a30 = fmaf(v0.w, w3, a30); a31 = fmaf(v1.w, w3, a31);
        }
        float* F0 = g_Fbuf[0] + base*128;
        F0[(g6*2  )*128 + c] = fmaxf(a30, 0.f);
        F0[(g6*2+1)*128 + c] = fmaxf(a31, 0.f);
    }
    grid_bar();

    // ================= 3 timesteps =================
    int cur = 0;
    #pragma unroll
    for (int s = 0; s < 3; s++) {
        // stage this step's weights in the background (first-use order)
        cpa(sG1, gW1 + s*8192, 8192);
        cpa(sG2, gW2 + s*2048, 2048);
        cpa_commit();                               // group G
        if (s < 2) {
            cpa(sF2, fW2 + (s+1)*8192, 8192);  cpa_commit();   // group F2
            cpa(sF3, fW3 + (s+1)*16384, 16384); cpa_commit();  // group F3
        }
        if (t < 96) sG3[t] = gW3[s*96 + t];

        // phase A: channelwise max over neighbors, 2 nodes/thread, ILP-8
        const float* Fn = g_Fbuf[cur] + n*MM*128;
        #pragma unroll
        for (int j = 0; j < 2; j++) {
            int i  = g6*2 + j;
            int dg = sD[i];
            const unsigned short* Ni = sN + i*MAXD;
            float m = 0.f;
            for (int d = 0; d < dg; d += 8) {
                float v0 = Fn[Ni[d+0]*128 + c], v1 = Fn[Ni[d+1]*128 + c];
                float v2 = Fn[Ni[d+2]*128 + c], v3 = Fn[Ni[d+3]*128 + c];
                float v4 = Fn[Ni[d+4]*128 + c], v5 = Fn[Ni[d+5]*128 + c];
                float v6 = Fn[Ni[d+6]*128 + c], v7 = Fn[Ni[d+7]*128 + c];
                float m01 = fmaxf(v0, v1), m23 = fmaxf(v2, v3);
                float m45 = fmaxf(v4, v5), m67 = fmaxf(v6, v7);
                m = fmaxf(m, fmaxf(fmaxf(m01, m23), fmaxf(m45, m67)));
            }
            sA[i*128 + c] = m;
        }
        if (s < 2) cpa_wait<2>(); else cpa_wait<0>();   // g-weights staged
        __syncthreads();

        // phase B: g layer1 (128 -> 64), 1 output/thread, float4 act loads
        {
            float a = bg1[s];
            const float* Ai = sA + n12*128;
            #pragma unroll 8
            for (int d = 0; d < 128; d += 4) {
                float4 v = *(const float4*)(Ai + d);
                a = fmaf(v.x, sG1[(d+0)*64 + k64], a);
                a = fmaf(v.y, sG1[(d+1)*64 + k64], a);
                a = fmaf(v.z, sG1[(d+2)*64 + k64], a);
                a = fmaf(v.w, sG1[(d+3)*64 + k64], a);
            }
            sB[n12*128 + k64] = fmaxf(a, 0.f);
        }
        __syncthreads();

        // phase C: g layer2 (64 -> 32), threads < 384, float4 act loads
        if (t < BN*32) {
            int k2 = t & 31, i12 = t >> 5;
            float a = bg2[s];
            const float* Bi = sB + i12*128;
            #pragma unroll
            for (int d = 0; d < 64; d += 4) {
                float4 v = *(const float4*)(Bi + d);
                a = fmaf(v.x, sG2[(d+0)*32 + k2], a);
                a = fmaf(v.y, sG2[(d+1)*32 + k2], a);
                a = fmaf(v.z, sG2[(d+2)*32 + k2], a);
                a = fmaf(v.w, sG2[(d+3)*32 + k2], a);
            }
            sA[i12*128 + k2] = fmaxf(a, 0.f);
        }
        __syncthreads();

        // phase D: g layer3 (32 -> 3) + relu + residual (state in regs)
        if (t < BN*3) {
            int i = t / 3, d = t % 3;
            float acc = bg3s[s];
            #pragma unroll
            for (int k3 = 0; k3 < 32; k3++)
                acc = fmaf(sA[i*128 + k3], sG3[k3*3 + d], acc);
            float ns = stv + fmaxf(acc, 0.f);
            stv = ns;
            if (s == 2) state[base*3 + t] = ns;    // final output, once
            else        sB[i*128 + d] = ns;        // feed next f phase
        }
        __syncthreads();

        if (s < 2) {
            // ---- MLP_f for step s+1 ----
            {
                float acc = bf1[s+1];
                acc = fmaf(sB[n12*128+0], w1a[s+1], acc);
                acc = fmaf(sB[n12*128+1], w1b[s+1], acc);
                acc = fmaf(sB[n12*128+2], w1c[s+1], acc);
                sA[n12*128 + k64] = fmaxf(acc, 0.f);
            }
            cpa_wait<1>();        // F2 staged
            __syncthreads();

            float a20 = bf2[s+1], a21 = bf2[s+1];
            const float* A0 = sA + (g6*2)*128, * A1 = A0 + 128;
            #pragma unroll
            for (int kk = 0; kk < 64; kk += 4) {
                float4 v0 = *(const float4*)(A0 + kk);
                float4 v1 = *(const float4*)(A1 + kk);
                float w0 = sF2[(kk+0)*128 + c], w1 = sF2[(kk+1)*128 + c];
                float w2 = sF2[(kk+2)*128 + c], w3 = sF2[(kk+3)*128 + c];
                a20 = fmaf(v0.x, w0, a20); a21 = fmaf(v1.x, w0, a21);
                a20 = fmaf(v0.y, w1, a20); a21 = fmaf(v1.y, w1, a21);
                a20 = fmaf(v0.z, w2, a20); a21 = fmaf(v1.z, w2, a21);
                a20 = fmaf(v0.w, w3, a20); a21 = fmaf(v1.w, w3, a21);
            }
            sB[(g6*2  )*128 + c] = fmaxf(a20, 0.f);
            sB[(g6*2+1)*128 + c] = fmaxf(a21, 0.f);
            cpa_wait<0>();        // F3 staged
            __syncthreads();

            float a30 = bf3[s+1], a31 = bf3[s+1];
            const float* B0 = sB + (g6*2)*128, * B1 = B0 + 128;
            #pragma unroll 8
            for (int kk = 0; kk < 128; kk += 4) {
                float4 v0 = *(const float4*)(B0 + kk);
                float4 v1 = *(const float4*)(B1 + kk);
                float w0 = sF3[(kk+0)*128 + c], w1 = sF3[(kk+1)*128 + c];
                float w2 = sF3[(kk+2)*128 + c], w3 = sF3[(kk+3)*128 + c];
                a30 = fmaf(v0.x, w0, a30); a31 = fmaf(v1.x, w0, a31);
                a30 = fmaf(v0.y, w1, a30); a31 = fmaf(v1.y, w1, a31);
                a30 = fmaf(v0.z, w2, a30); a31 = fmaf(v1.z, w2, a31);
                a30 = fmaf(v0.w, w3, a30); a31 = fmaf(v1.w, w3, a31);
            }
            float* Fo = g_Fbuf[cur ^ 1] + base*128;
            Fo[(g6*2  )*128 + c] = fmaxf(a30, 0.f);
            Fo[(g6*2+1)*128 + c] = fmaxf(a31, 0.f);

            grid_bar();
            cur ^= 1;
        }
    }
}

// ---------------------------------------------------------------------------
extern "C" void kernel_launch(void* const* d_in, const int* in_sizes, int n_in,
                              void* d_out, int out_size) {
    const float* x   = (const float*)d_in[0];
    const float* fW1 = (const float*)d_in[7];
    const float* fb1 = (const float*)d_in[8];
    const float* fW2 = (const float*)d_in[9];
    const float* fb2 = (const float*)d_in[10];
    const float* fW3 = (const float*)d_in[11];
    const float* fb3 = (const float*)d_in[12];
    const float* gW1 = (const float*)d_in[13];
    const float* gb1 = (const float*)d_in[14];
    const float* gW2 = (const float*)d_in[15];
    const float* gb2 = (const float*)d_in[16];
    const float* gW3 = (const float*)d_in[17];
    const float* gb3 = (const float*)d_in[18];
    float* state = (float*)d_out;

    cudaFuncSetAttribute(pointgnn_persistent,
                         cudaFuncAttributeMaxDynamicSharedMemorySize, SMEM_BYTES);

    pointgnn_persistent<<<GRID, TPB, SMEM_BYTES>>>(x, state,
        fW1, fb1, fW2, fb2, fW3, fb3,
        gW1, gb1, gW2, gb2, gW3, gb3);
}

// round 13
// speedup vs baseline: 1.1196x; 1.1196x over previous
#include <cuda_runtime.h>
#include <cuda_bf16.h>

// PointGNN, algebraically reduced, single persistent kernel, 1 block/SM,
// per-step weights staged via background cp.async into big dynamic smem.
//   adj(i) = { j : |x_i - x_j|^2 < 0.05 }  (fixed; self always in-set)
//   F_t[j]   = MLP_f([0,0,0,state_j])      (per NODE, not per edge)
//   agg_t[i] = max_{j in adj(i)} F_t[j]    (channelwise; F>=0 so 0-floor exact)
//   state   += relu(MLP_g(agg_t))
// h-MLP provably dead. Neighbor lists fully padded with self (exact under max)
// so the max phase can interleave 4 nodes x 8 loads. g_F double-buffered;
// 3 grid barriers; GRID=128 <= 148 SMs -> 1 co-resident block/SM (barrier safe).

#define MM    384
#define NODES (4*MM)
#define MASKW 12
#define BN    12
#define TPB   384
#define GRID  (NODES/BN)   // 128
#define MAXD  128

// dynamic smem layout (floats unless noted):
//   sG1 8192 | sG2 2048 | sF2 8192 | sF3 16384 | sA 1536 | sB 1536 | sG3 96
//   | sN 1536 u16 | sD 12 int     => 155,056 bytes
#define SMEM_BYTES 155056

__device__ float    g_Fbuf[2][NODES * 128];
__device__ unsigned g_bar;   // monotonic; wrap-safe barrier

__device__ __forceinline__ void cpa(float* dst, const float* src, int nfloats) {
    for (int idx = threadIdx.x * 4; idx < nfloats; idx += TPB * 4) {
        unsigned sa = (unsigned)__cvta_generic_to_shared(dst + idx);
        asm volatile("cp.async.cg.shared.global [%0], [%1], 16;"
                     :: "r"(sa), "l"(src + idx));
    }
}
__device__ __forceinline__ void cpa_commit() {
    asm volatile("cp.async.commit_group;");
}
template<int N> __device__ __forceinline__ void cpa_wait() {
    asm volatile("cp.async.wait_group %0;" :: "n"(N));
}

// grid-wide barrier: monotonic ticket counter, wrap-safe compare
__device__ __forceinline__ void grid_bar() {
    __syncthreads();
    if (threadIdx.x == 0) {
        __threadfence();
        unsigned v = atomicAdd(&g_bar, 1u);
        unsigned target = v - (v % (unsigned)GRID) + (unsigned)GRID;
        unsigned cur;
        do {
            asm volatile("ld.acquire.gpu.u32 %0, [%1];" : "=r"(cur) : "l"(&g_bar));
        } while ((int)(cur - target) < 0);
    }
    __syncthreads();
}

// ---------------------------------------------------------------------------
__global__ __launch_bounds__(TPB) void pointgnn_persistent(
    const float* x, float* state,
    const float* fW1, const float* fb1, const float* fW2, const float* fb2,
    const float* fW3, const float* fb3,
    const float* gW1, const float* gb1, const float* gW2, const float* gb2,
    const float* gW3, const float* gb3)
{
    extern __shared__ float sm[];
    float*          sG1 = sm;                 // 8192
    float*          sG2 = sG1 + 8192;         // 2048
    float*          sF2 = sG2 + 2048;         // 8192
    float*          sF3 = sF2 + 8192;         // 16384
    float*          sA  = sF3 + 16384;        // 12 x 128
    float*          sB  = sA + 1536;          // 12 x 128
    float*          sG3 = sB + 1536;          // 96
    unsigned short* sN  = (unsigned short*)(sG3 + 96);   // 12 x 128
    int*            sD  = (int*)(sN + BN*MAXD);          // 12

    const int t    = threadIdx.x;
    const int base = blockIdx.x * BN;        // 12 nodes, same batch (384%12==0)
    const int n    = base / MM;
    const int c    = t & 127;                // channel lane
    const int g3c  = t >> 7;                 // 0..2 -> node quad
    const int k64  = t & 63;
    const int h6   = t >> 6;                 // 0..5 -> node pair

    // ---- stage f0 weights immediately (overlap adjacency build) ----
    cpa(sF2, fW2, 8192);  cpa_commit();      // group: F2
    cpa(sF3, fW3, 16384); cpa_commit();      // group: F3

    // ---- one-time prefetch: all 3 steps' biases + state + fW1 rows ----
    float bf1[3], bf2[3], bf3[3], bg1[3], bg2[3], bg3s[3];
    float w1a[3], w1b[3], w1c[3];
    #pragma unroll
    for (int s = 0; s < 3; s++) {
        bf1[s] = fb1[s*64  + k64];
        bf2[s] = fb2[s*128 + c];
        bf3[s] = fb3[s*128 + c];
        bg1[s] = gb1[s*64  + k64];
        bg2[s] = gb2[s*32  + (t & 31)];
        w1a[s] = fW1[s*384 + 3*64 + k64];
        w1b[s] = fW1[s*384 + 4*64 + k64];
        w1c[s] = fW1[s*384 + 5*64 + k64];
    }
    float stv = 0.f;
    if (t < BN*3) {
        stv = x[base*3 + t];
        #pragma unroll
        for (int s = 0; s < 3; s++) bg3s[s] = gb3[s*3 + t % 3];
    }

    // ---- adjacency (once, pure smem): warp-per-node popc compaction.
    //      Lists padded to MAXD with self -> safe to scan past own degree. ----
    {
        const int warp = t >> 5, lane = t & 31;   // 12 warps = 12 nodes
        const int i = base + warp;
        float xi0 = x[i*3+0], xi1 = x[i*3+1], xi2 = x[i*3+2];
        int cnt = 0;
        #pragma unroll
        for (int wc = 0; wc < MASKW; wc++) {
            int j = wc*32 + lane;
            const float* xj = x + (n*MM + j)*3;
            float dx = xi0 - xj[0], dy = xi1 - xj[1], dz = xi2 - xj[2];
            // non-contracted to match reference's (diff*diff).sum() compare
            float s2 = __fadd_rn(__fadd_rn(__fmul_rn(dx,dx), __fmul_rn(dy,dy)),
                                 __fmul_rn(dz,dz));
            bool pred = s2 < 0.05f;
            unsigned m = __ballot_sync(0xffffffffu, pred);
            int pos = cnt + __popc(m & ((1u << lane) - 1u));
            if (pred && pos < MAXD) sN[warp*MAXD + pos] = (unsigned short)j;
            cnt += __popc(m);
        }
        int cl = cnt < MAXD ? cnt : MAXD;
        unsigned short self = (unsigned short)(i - n*MM);
        for (int p = cl + lane; p < MAXD; p += 32) sN[warp*MAXD + p] = self;
        if (lane == 0) sD[warp] = (cl + 7) & ~7;
    }
    if (t < BN*3) sB[(t/3)*128 + t%3] = stv;       // state := x
    __syncthreads();

    // ================= F0 = MLP_f(x) =================
    {
        // layer1 (rows 3..5 only, weights in regs)
        #pragma unroll
        for (int j = 0; j < 2; j++) {
            int i = h6*2 + j;
            float acc = bf1[0];
            acc = fmaf(sB[i*128+0], w1a[0], acc);
            acc = fmaf(sB[i*128+1], w1b[0], acc);
            acc = fmaf(sB[i*128+2], w1c[0], acc);
            sA[i*128 + k64] = fmaxf(acc, 0.f);
        }
        cpa_wait<1>();        // F2 staged (F3 may still be in flight)
        __syncthreads();

        // layer2: 64 -> 128, ILP-4
        float acc2[4];
        #pragma unroll
        for (int j = 0; j < 4; j++) acc2[j] = bf2[0];
        #pragma unroll 4
        for (int kk = 0; kk < 64; kk++) {
            float w = sF2[kk*128 + c];
            #pragma unroll
            for (int j = 0; j < 4; j++)
                acc2[j] = fmaf(sA[(g3c*4 + j)*128 + kk], w, acc2[j]);
        }
        #pragma unroll
        for (int j = 0; j < 4; j++) sB[(g3c*4 + j)*128 + c] = fmaxf(acc2[j], 0.f);
        cpa_wait<0>();        // F3 staged
        __syncthreads();

        // layer3: 128 -> 128 single pass, split-k: 4 nodes x 2 partials
        float accA[4], accB[4];
        #pragma unroll
        for (int j = 0; j < 4; j++) { accA[j] = bf3[0]; accB[j] = 0.f; }
        #pragma unroll 4
        for (int kk = 0; kk < 64; kk++) {
            float wA = sF3[kk*128 + c];
            float wB = sF3[(kk+64)*128 + c];
            #pragma unroll
            for (int j = 0; j < 4; j++) {
                accA[j] = fmaf(sA ? 0.f*0.f : 0.f, 0.f, accA[j]); // placeholder removed below
            }
        }
        // (rewritten cleanly below)
        float* F0 = g_Fbuf[0] + base*128;
        #pragma unroll
        for (int j = 0; j < 4; j++) { accA[j] = bf3[0]; accB[j] = 0.f; }
        #pragma unroll 4
        for (int kk = 0; kk < 64; kk++) {
            float wA = sF3[kk*128 + c];
            float wB = sF3[(kk+64)*128 + c];
            #pragma unroll
            for (int j = 0; j < 4; j++) {
                accA[j] = fmaf(sB[(g3c*4 + j)*128 + kk],      wA, accA[j]);
                accB[j] = fmaf(sB[(g3c*4 + j)*128 + kk + 64], wB, accB[j]);
            }
        }
        #pragma unroll
        for (int j = 0; j < 4; j++)
            F0[(g3c*4 + j)*128 + c] = fmaxf(accA[j] + accB[j], 0.f);
    }
    grid_bar();

    // ================= 3 timesteps =================
    int cur = 0;
    #pragma unroll
    for (int s = 0; s < 3; s++) {
        // stage this step's weights in the background (first-use order)
        cpa(sG1, gW1 + s*8192, 8192);
        cpa(sG2, gW2 + s*2048, 2048);
        cpa_commit();                               // group G
        if (s < 2) {
            cpa(sF2, fW2 + (s+1)*8192, 8192);  cpa_commit();   // group F2
            cpa(sF3, fW3 + (s+1)*16384, 16384); cpa_commit();  // group F3
        }
        if (t < 96) sG3[t] = gW3[s*96 + t];

        // phase A: channelwise max, 4 nodes interleaved -> 32 loads in flight
        {
            const float* Fn = g_Fbuf[cur] + n*MM*128;
            const int i0 = g3c*4;
            int dgq = sD[i0];
            dgq = max(dgq, sD[i0+1]); dgq = max(dgq, sD[i0+2]); dgq = max(dgq, sD[i0+3]);
            float mx[4] = {0.f, 0.f, 0.f, 0.f};
            for (int d = 0; d < dgq; d += 8) {
                float v[4][8];
                #pragma unroll
                for (int j = 0; j < 4; j++) {
                    const unsigned short* Ni = sN + (i0 + j)*MAXD + d;
                    #pragma unroll
                    for (int e = 0; e < 8; e++) v[j][e] = Fn[Ni[e]*128 + c];
                }
                #pragma unroll
                for (int j = 0; j < 4; j++) {
                    float m01 = fmaxf(v[j][0], v[j][1]), m23 = fmaxf(v[j][2], v[j][3]);
                    float m45 = fmaxf(v[j][4], v[j][5]), m67 = fmaxf(v[j][6], v[j][7]);
                    mx[j] = fmaxf(mx[j], fmaxf(fmaxf(m01, m23), fmaxf(m45, m67)));
                }
            }
            #pragma unroll
            for (int j = 0; j < 4; j++) sA[(i0 + j)*128 + c] = mx[j];
        }
        if (s < 2) cpa_wait<2>(); else cpa_wait<0>();   // g-weights staged
        __syncthreads();

        // phase B: g layer1 (128 -> 64), 2 nodes x 2 split-k partials
        {
            float a0A = bg1[s], a0B = 0.f, a1A = bg1[s], a1B = 0.f;
            const float* A0 = sA + (h6*2)*128, * A1 = A0 + 128;
            #pragma unroll 8
            for (int d = 0; d < 64; d++) {
                float wA = sG1[d*64 + k64];
                float wB = sG1[(d+64)*64 + k64];
                a0A = fmaf(A0[d],      wA, a0A);
                a0B = fmaf(A0[d + 64], wB, a0B);
                a1A = fmaf(A1[d],      wA, a1A);
                a1B = fmaf(A1[d + 64], wB, a1B);
            }
            sB[(h6*2    )*128 + k64] = fmaxf(a0A + a0B, 0.f);
            sB[(h6*2 + 1)*128 + k64] = fmaxf(a1A + a1B, 0.f);
        }
        __syncthreads();

        // phase C: g layer2 (64 -> 32), split-k 2 partials
        {
            int k2 = t & 31, i12 = t >> 5;
            float aA = bg2[s], aB = 0.f;
            const float* Bi = sB + i12*128;
            #pragma unroll 8
            for (int d = 0; d < 32; d++) {
                aA = fmaf(Bi[d],      sG2[d*32 + k2],      aA);
                aB = fmaf(Bi[d + 32], sG2[(d+32)*32 + k2], aB);
            }
            sA[i12*128 + k2] = fmaxf(aA + aB, 0.f);
        }
        __syncthreads();

        // phase D: g layer3 (32 -> 3) + relu + residual (state in regs)
        if (t < BN*3) {
            int i = t / 3, d = t % 3;
            float acc = bg3s[s];
            #pragma unroll
            for (int k3 = 0; k3 < 32; k3++)
                acc = fmaf(sA[i*128 + k3], sG3[k3*3 + d], acc);
            float ns = stv + fmaxf(acc, 0.f);
            stv = ns;
            if (s == 2) state[base*3 + t] = ns;    // final output, once
            else        sB[i*128 + d] = ns;        // feed next f phase
        }
        __syncthreads();

        if (s < 2) {
            // ---- MLP_f for step s+1 ----
            #pragma unroll
            for (int j = 0; j < 2; j++) {
                int i = h6*2 + j;
                float acc = bf1[s+1];
                acc = fmaf(sB[i*128+0], w1a[s+1], acc);
                acc = fmaf(sB[i*128+1], w1b[s+1], acc);
                acc = fmaf(sB[i*128+2], w1c[s+1], acc);
                sA[i*128 + k64] = fmaxf(acc, 0.f);
            }
            cpa_wait<1>();        // F2 staged
            __syncthreads();

            float acc2[4];
            #pragma unroll
            for (int j = 0; j < 4; j++) acc2[j] = bf2[s+1];
            #pragma unroll 4
            for (int kk = 0; kk < 64; kk++) {
                float w = sF2[kk*128 + c];
                #pragma unroll
                for (int j = 0; j < 4; j++)
                    acc2[j] = fmaf(sA[(g3c*4 + j)*128 + kk], w, acc2[j]);
            }
            #pragma unroll
            for (int j = 0; j < 4; j++)
                sB[(g3c*4 + j)*128 + c] = fmaxf(acc2[j], 0.f);
            cpa_wait<0>();        // F3 staged
            __syncthreads();

            // layer3 split-k: 4 nodes x 2 partials
            float accA[4], accB[4];
            #pragma unroll
            for (int j = 0; j < 4; j++) { accA[j] = bf3[s+1]; accB[j] = 0.f; }
            #pragma unroll 4
            for (int kk = 0; kk < 64; kk++) {
                float wA = sF3[kk*128 + c];
                float wB = sF3[(kk+64)*128 + c];
                #pragma unroll
                for (int j = 0; j < 4; j++) {
                    accA[j] = fmaf(sB[(g3c*4 + j)*128 + kk],      wA, accA[j]);
                    accB[j] = fmaf(sB[(g3c*4 + j)*128 + kk + 64], wB, accB[j]);
                }
            }
            float* Fo = g_Fbuf[cur ^ 1] + base*128;
            #pragma unroll
            for (int j = 0; j < 4; j++)
                Fo[(g3c*4 + j)*128 + c] = fmaxf(accA[j] + accB[j], 0.f);

            grid_bar();
            cur ^= 1;
        }
    }
}

// ---------------------------------------------------------------------------
extern "C" void kernel_launch(void* const* d_in, const int* in_sizes, int n_in,
                              void* d_out, int out_size) {
    const float* x   = (const float*)d_in[0];
    const float* fW1 = (const float*)d_in[7];
    const float* fb1 = (const float*)d_in[8];
    const float* fW2 = (const float*)d_in[9];
    const float* fb2 = (const float*)d_in[10];
    const float* fW3 = (const float*)d_in[11];
    const float* fb3 = (const float*)d_in[12];
    const float* gW1 = (const float*)d_in[13];
    const float* gb1 = (const float*)d_in[14];
    const float* gW2 = (const float*)d_in[15];
    const float* gb2 = (const float*)d_in[16];
    const float* gW3 = (const float*)d_in[17];
    const float* gb3 = (const float*)d_in[18];
    float* state = (float*)d_out;

    cudaFuncSetAttribute(pointgnn_persistent,
                         cudaFuncAttributeMaxDynamicSharedMemorySize, SMEM_BYTES);

    pointgnn_persistent<<<GRID, TPB, SMEM_BYTES>>>(x, state,
        fW1, fb1, fW2, fb2, fW3, fb3,
        gW1, gb1, gW2, gb2, gW3, gb3);
}